// round 16
// baseline (speedup 1.0000x reference)
#include <cuda_runtime.h>
#include <cuda_fp16.h>
#include <cstdint>
#include <math.h>

typedef unsigned int u32;

#define D_MODEL 1024
#define NH 16
#define DK 64
#define BATCH 2
#define SEQ 2048
#define M_ROWS (BATCH * SEQ)   // 4096

#define NEG_INF (__int_as_float(0xff800000))
#define LOG2_10000 13.287712379549449f
#define SCALE_Q 0.1803368801111244f   // 0.125 * log2(e): base-2 softmax

// ---------------------------------------------------------------------------
// Scratch
// ---------------------------------------------------------------------------
__device__ __half g_xh[(size_t)M_ROWS * D_MODEL];
__device__ __half g_xl[(size_t)M_ROWS * D_MODEL];
__device__ __half g_ah[(size_t)M_ROWS * D_MODEL];
__device__ __half g_al[(size_t)M_ROWS * D_MODEL];
__device__ __half g_wh[4ull * D_MODEL * D_MODEL];

#define HM_ELEMS ((size_t)BATCH * NH * SEQ * DK)
__device__ __half g_qh[HM_ELEMS];
__device__ __half g_ql[HM_ELEMS];
__device__ __half g_kh[HM_ELEMS];
__device__ __half g_vh[HM_ELEMS];

// ---------------------------------------------------------------------------
// helpers
// ---------------------------------------------------------------------------
__device__ __forceinline__ void split2h(float a, float b, u32* hp, u32* lp)
{
    __half2 h = __floats2half2_rn(a, b);
    float2 hf = __half22float2(h);
    __half2 l = __floats2half2_rn(a - hf.x, b - hf.y);
    *hp = *(u32*)&h;
    *lp = *(u32*)&l;
}

__device__ __forceinline__ u32 pack2h(float a, float b)
{
    __half2 h = __floats2half2_rn(a, b);
    return *(u32*)&h;
}

__device__ __forceinline__ void ldsm_x4(u32* r, const __half* p)
{
    u32 a = (u32)__cvta_generic_to_shared(p);
    asm volatile("ldmatrix.sync.aligned.m8n8.x4.shared.b16 {%0,%1,%2,%3}, [%4];"
        : "=r"(r[0]), "=r"(r[1]), "=r"(r[2]), "=r"(r[3]) : "r"(a));
}

__device__ __forceinline__ void ldsm_x2(u32* r, const __half* p)
{
    u32 a = (u32)__cvta_generic_to_shared(p);
    asm volatile("ldmatrix.sync.aligned.m8n8.x2.shared.b16 {%0,%1}, [%2];"
        : "=r"(r[0]), "=r"(r[1]) : "r"(a));
}

__device__ __forceinline__ void ldsm_x4t(u32* r, const __half* p)
{
    u32 a = (u32)__cvta_generic_to_shared(p);
    asm volatile("ldmatrix.sync.aligned.m8n8.x4.trans.shared.b16 {%0,%1,%2,%3}, [%4];"
        : "=r"(r[0]), "=r"(r[1]), "=r"(r[2]), "=r"(r[3]) : "r"(a));
}

__device__ __forceinline__ void mma16816(float* d, const u32* a, const u32* b)
{
    asm volatile("mma.sync.aligned.m16n8k16.row.col.f32.f16.f16.f32 "
        "{%0,%1,%2,%3}, {%4,%5,%6,%7}, {%8,%9}, {%0,%1,%2,%3};"
        : "+f"(d[0]), "+f"(d[1]), "+f"(d[2]), "+f"(d[3])
        : "r"(a[0]), "r"(a[1]), "r"(a[2]), "r"(a[3]), "r"(b[0]), "r"(b[1]));
}

// ---------------------------------------------------------------------------
// Splits / converts
// ---------------------------------------------------------------------------
__global__ void split_x(const float* __restrict__ in,
                        __half* __restrict__ hi, __half* __restrict__ lo, int n4)
{
    int i = blockIdx.x * blockDim.x + threadIdx.x;
    if (i >= n4) return;
    float4 v = ((const float4*)in)[i];
    u32 h0, l0, h1, l1;
    split2h(v.x, v.y, &h0, &l0);
    split2h(v.z, v.w, &h1, &l1);
    u32* hp = (u32*)(hi + 4 * (size_t)i);
    u32* lp = (u32*)(lo + 4 * (size_t)i);
    hp[0] = h0;
    hp[1] = h1;
    lp[0] = l0;
    lp[1] = l1;
}

__global__ void convert_w4(const float* __restrict__ W0, const float* __restrict__ W1,
                           const float* __restrict__ W2, const float* __restrict__ W3,
                           __half* __restrict__ out, int n4)
{
    int i = blockIdx.x * blockDim.x + threadIdx.x;
    if (i >= n4) return;
    int wsel = blockIdx.y;
    const float* W = (wsel == 0) ? W0 : (wsel == 1) ? W1 : (wsel == 2) ? W2 : W3;
    size_t off = (size_t)wsel * D_MODEL * D_MODEL;
    float4 v = ((const float4*)W)[i];
    __half2 h0 = __floats2half2_rn(v.x, v.y);
    __half2 h1 = __floats2half2_rn(v.z, v.w);
    u32* hp = (u32*)(out + off + 4 * (size_t)i);
    hp[0] = *(u32*)&h0;
    hp[1] = *(u32*)&h1;
}

// ---------------------------------------------------------------------------
// 2-pass fp16 GEMM, 128x128 tile, templated epilogue (unchanged, proven):
//   MODE 0: plain fp32 C store.
//   MODE 1: fused QKV epilogue — RoPE(Q,K) + fp16 convert/split + head-major.
// ---------------------------------------------------------------------------
#define BM 128
#define BN 128
#define BKT 32
#define LDT 40

template<int MODE>
__global__ void __launch_bounds__(256) gemm_2p(
    const __half* __restrict__ Ahi, const __half* __restrict__ Alo,
    const __half* __restrict__ B,
    float* __restrict__ C,
    __half* __restrict__ qh, __half* __restrict__ ql,
    __half* __restrict__ kh, __half* __restrict__ vh,
    int M, int N, int K)
{
    __shared__ __align__(16) __half sAh[BM][LDT];
    __shared__ __align__(16) __half sAl[BM][LDT];
    __shared__ __align__(16) __half sB[BN][LDT];

    const int tid  = threadIdx.x;
    const int lane = tid & 31;
    const int warp = tid >> 5;
    const int m0 = blockIdx.y * BM;
    const int n0 = blockIdx.x * BN;
    const int wm = (warp & 1) * 64;
    const int wn = (warp >> 1) * 32;

    float acc[4][4][4];
#pragma unroll
    for (int mt = 0; mt < 4; mt++) {
#pragma unroll
        for (int nt = 0; nt < 4; nt++) {
#pragma unroll
            for (int q = 0; q < 4; q++) {
                acc[mt][nt][q] = 0.f;
            }
        }
    }

    for (int k0 = 0; k0 < K; k0 += BKT) {
#pragma unroll
        for (int p = 0; p < 2; p++) {
            int idx = tid + p * 256;
            int r = idx >> 2;
            int c = (idx & 3) * 8;
            *(uint4*)&sAh[r][c] = *(const uint4*)&Ahi[(size_t)(m0 + r) * K + k0 + c];
            *(uint4*)&sAl[r][c] = *(const uint4*)&Alo[(size_t)(m0 + r) * K + k0 + c];
            *(uint4*)&sB[r][c]  = *(const uint4*)&B[(size_t)(n0 + r) * K + k0 + c];
        }
        __syncthreads();

#pragma unroll
        for (int ks = 0; ks < 2; ks++) {
            const int kk = ks * 16;
            u32 ah[4][4];
            u32 al[4][4];
            u32 bh[4][2];
#pragma unroll
            for (int mt = 0; mt < 4; mt++) {
                const int rr = wm + mt * 16 + (lane & 15);
                const int cc = kk + (lane >> 4) * 8;
                ldsm_x4(ah[mt], &sAh[rr][cc]);
                ldsm_x4(al[mt], &sAl[rr][cc]);
            }
#pragma unroll
            for (int nt = 0; nt < 4; nt++) {
                const int rr = wn + nt * 8 + (lane & 7);
                const int cc = kk + ((lane >> 3) & 1) * 8;
                ldsm_x2(bh[nt], &sB[rr][cc]);
            }
#pragma unroll
            for (int mt = 0; mt < 4; mt++) {
#pragma unroll
                for (int nt = 0; nt < 4; nt++) {
                    mma16816(acc[mt][nt], ah[mt], bh[nt]);
                    mma16816(acc[mt][nt], al[mt], bh[nt]);
                }
            }
        }
        __syncthreads();
    }

    if (MODE == 0) {
#pragma unroll
        for (int mt = 0; mt < 4; mt++) {
#pragma unroll
            for (int nt = 0; nt < 4; nt++) {
                const int row = m0 + wm + mt * 16 + (lane >> 2);
                const int col = n0 + wn + nt * 8 + (lane & 3) * 2;
                float2 v0;
                v0.x = acc[mt][nt][0];
                v0.y = acc[mt][nt][1];
                float2 v1;
                v1.x = acc[mt][nt][2];
                v1.y = acc[mt][nt][3];
                *(float2*)&C[(size_t)row * N + col] = v0;
                *(float2*)&C[(size_t)(row + 8) * N + col] = v1;
            }
        }
    } else {
        // fused QKV epilogue: col in [0,3072): 0-1023 Q, 1024-2047 K, 2048-3071 V
#pragma unroll
        for (int nt = 0; nt < 4; nt++) {
            const int col = n0 + wn + nt * 8 + (lane & 3) * 2;
            const int wsel = col >> 10;
            const int hcol = col & 1023;
            const int hh = hcol >> 6;
            const int d = hcol & 63;     // even element of the RoPE pair
            const float freq = exp2f(-((float)d / 64.0f) * LOG2_10000);
#pragma unroll
            for (int mt = 0; mt < 4; mt++) {
#pragma unroll
                for (int half_i = 0; half_i < 2; half_i++) {
                    const int row = m0 + wm + mt * 16 + (lane >> 2) + half_i * 8;
                    const int s = row & (SEQ - 1);
                    const int b = row >> 11;
                    const float v0 = acc[mt][nt][half_i * 2];
                    const float v1 = acc[mt][nt][half_i * 2 + 1];
                    const size_t dst =
                        ((size_t)(b * NH + hh) * SEQ + s) * DK + d;
                    if (wsel == 0) {
                        float sn, cc;
                        __sincosf((float)s * freq, &sn, &cc);
                        float r1 = (v0 * cc - v1 * sn) * SCALE_Q;
                        float r2 = (v0 * sn + v1 * cc) * SCALE_Q;
                        u32 h2, l2;
                        split2h(r1, r2, &h2, &l2);
                        *(u32*)&qh[dst] = h2;
                        *(u32*)&ql[dst] = l2;
                    } else if (wsel == 1) {
                        float sn, cc;
                        __sincosf((float)s * freq, &sn, &cc);
                        float r1 = v0 * cc - v1 * sn;
                        float r2 = v0 * sn + v1 * cc;
                        *(u32*)&kh[dst] = pack2h(r1, r2);
                    } else {
                        *(u32*)&vh[dst] = pack2h(v0, v1);
                    }
                }
            }
        }
    }
}

// ---------------------------------------------------------------------------
// MMA flash attention v5:
//  - double-buffered K/V smem + register prefetch of tile jt+1 under compute jt
//  - ONE __syncthreads per KV tile
//  - Q (hi/lo) resident in smem; fragments re-materialized per kc-pair
//  - base-2 softmax; P single fp16; wide ldmatrix; longest-first scheduling
// ---------------------------------------------------------------------------
__global__ void __launch_bounds__(128, 4) attn_mma(
    const __half* __restrict__ qh_, const __half* __restrict__ ql_,
    const __half* __restrict__ kh_, const __half* __restrict__ vh_,
    __half* __restrict__ ohi, __half* __restrict__ olo)
{
    __shared__ __align__(16) __half sQh[64][72];
    __shared__ __align__(16) __half sQl[64][72];
    __shared__ __align__(16) __half sK[2][64][72];
    __shared__ __align__(16) __half sV[2][64][72];

    const int qt = gridDim.x - 1 - blockIdx.x;   // longest-first
    const int hb = blockIdx.y;
    const int t = threadIdx.x;
    const int lane = t & 31;
    const int w = t >> 5;
    const size_t base = (size_t)hb * (SEQ * DK);
    const int q0 = qt * 64;

    // per-thread load slots: 4 uint4 per array (512 uint4 total / 128 threads)
    const int lr = t >> 1;               // row 0..63
    const int lc = (t & 1) * 32;         // col 0 or 32 (in halves)

    // Q tile resident in smem; preload KV tile 0 into stage 0
    for (int i = t; i < 512; i += 128) {
        int r = i >> 3, c = (i & 7) * 8;
        *(uint4*)&sQh[r][c] = *(const uint4*)&qh_[base + (size_t)(q0 + r) * DK + c];
        *(uint4*)&sQl[r][c] = *(const uint4*)&ql_[base + (size_t)(q0 + r) * DK + c];
    }
#pragma unroll
    for (int i = 0; i < 4; i++) {
        const size_t g = base + (size_t)lr * DK + lc + i * 8;
        *(uint4*)&sK[0][lr][lc + i * 8] = *(const uint4*)&kh_[g];
        *(uint4*)&sV[0][lr][lc + i * 8] = *(const uint4*)&vh_[g];
    }
    __syncthreads();

    float m0 = NEG_INF, m1 = NEG_INF, l0 = 0.f, l1 = 0.f;
    float O[8][4];
#pragma unroll
    for (int nt = 0; nt < 8; nt++) {
#pragma unroll
        for (int q = 0; q < 4; q++) O[nt][q] = 0.f;
    }

    for (int jt = 0; jt <= qt; jt++) {
        const int cur = jt & 1;

        // issue prefetch of tile jt+1 into registers (latency hidden by compute)
        uint4 kreg[4];
        uint4 vreg[4];
        if (jt < qt) {
            const size_t gb = base + (size_t)(jt + 1) * 64 * DK + (size_t)lr * DK + lc;
#pragma unroll
            for (int i = 0; i < 4; i++) {
                kreg[i] = *(const uint4*)&kh_[gb + i * 8];
                vreg[i] = *(const uint4*)&vh_[gb + i * 8];
            }
        }

        // S = Q @ K^T; Q fragments re-materialized per kc-pair
        float S[8][4];
#pragma unroll
        for (int nt = 0; nt < 8; nt++) {
#pragma unroll
            for (int q = 0; q < 4; q++) S[nt][q] = 0.f;
        }
#pragma unroll
        for (int kcp = 0; kcp < 2; kcp++) {
            u32 qfh[2][4];
            u32 qfl[2][4];
#pragma unroll
            for (int kk = 0; kk < 2; kk++) {
                const int kc = kcp * 2 + kk;
                const int rr = w * 16 + (lane & 15);
                const int cc = kc * 16 + (lane >> 4) * 8;
                ldsm_x4(qfh[kk], &sQh[rr][cc]);
                ldsm_x4(qfl[kk], &sQl[rr][cc]);
            }
#pragma unroll
            for (int nt = 0; nt < 8; nt++) {
                u32 kb[4];
                const int rr = nt * 8 + (lane & 7);
                ldsm_x4(kb, &sK[cur][rr][kcp * 32 + (lane >> 3) * 8]);
                mma16816(S[nt], qfh[0], &kb[0]);
                mma16816(S[nt], qfl[0], &kb[0]);
                mma16816(S[nt], qfh[1], &kb[2]);
                mma16816(S[nt], qfl[1], &kb[2]);
            }
        }

        // causal mask + online softmax (base 2)
        const bool diag = (jt == qt);
        const int rowm = w * 16 + (lane >> 2);
        float tm0 = NEG_INF, tm1 = NEG_INF;
#pragma unroll
        for (int nt = 0; nt < 8; nt++) {
            const int cn = nt * 8 + (lane & 3) * 2;
            if (diag) {
                if (cn > rowm)         S[nt][0] = NEG_INF;
                if (cn + 1 > rowm)     S[nt][1] = NEG_INF;
                if (cn > rowm + 8)     S[nt][2] = NEG_INF;
                if (cn + 1 > rowm + 8) S[nt][3] = NEG_INF;
            }
            tm0 = fmaxf(tm0, fmaxf(S[nt][0], S[nt][1]));
            tm1 = fmaxf(tm1, fmaxf(S[nt][2], S[nt][3]));
        }
        tm0 = fmaxf(tm0, __shfl_xor_sync(0xffffffffu, tm0, 1));
        tm0 = fmaxf(tm0, __shfl_xor_sync(0xffffffffu, tm0, 2));
        tm1 = fmaxf(tm1, __shfl_xor_sync(0xffffffffu, tm1, 1));
        tm1 = fmaxf(tm1, __shfl_xor_sync(0xffffffffu, tm1, 2));

        const float mn0 = fmaxf(m0, tm0);
        const float mn1 = fmaxf(m1, tm1);
        const float a0 = exp2f(m0 - mn0);
        const float a1 = exp2f(m1 - mn1);

        float ps0 = 0.f, ps1 = 0.f;
#pragma unroll
        for (int nt = 0; nt < 8; nt++) {
            S[nt][0] = exp2f(S[nt][0] - mn0);
            S[nt][1] = exp2f(S[nt][1] - mn0);
            S[nt][2] = exp2f(S[nt][2] - mn1);
            S[nt][3] = exp2f(S[nt][3] - mn1);
            ps0 += S[nt][0] + S[nt][1];
            ps1 += S[nt][2] + S[nt][3];
        }
        ps0 += __shfl_xor_sync(0xffffffffu, ps0, 1);
        ps0 += __shfl_xor_sync(0xffffffffu, ps0, 2);
        ps1 += __shfl_xor_sync(0xffffffffu, ps1, 1);
        ps1 += __shfl_xor_sync(0xffffffffu, ps1, 2);
        l0 = l0 * a0 + ps0;
        l1 = l1 * a1 + ps1;
#pragma unroll
        for (int nt = 0; nt < 8; nt++) {
            O[nt][0] *= a0;
            O[nt][1] *= a0;
            O[nt][2] *= a1;
            O[nt][3] *= a1;
        }
        m0 = mn0;
        m1 = mn1;

        // O += P @ V, single-pass P fp16
#pragma unroll
        for (int kc = 0; kc < 4; kc++) {
            u32 ph[4];
            ph[0] = pack2h(S[2 * kc][0], S[2 * kc][1]);
            ph[1] = pack2h(S[2 * kc][2], S[2 * kc][3]);
            ph[2] = pack2h(S[2 * kc + 1][0], S[2 * kc + 1][1]);
            ph[3] = pack2h(S[2 * kc + 1][2], S[2 * kc + 1][3]);
            const int rr = kc * 16 + (lane & 15);
#pragma unroll
            for (int ntp = 0; ntp < 4; ntp++) {
                u32 vb4[4];
                ldsm_x4t(vb4, &sV[cur][rr][ntp * 16 + (lane >> 4) * 8]);
                mma16816(O[2 * ntp],     ph, &vb4[0]);
                mma16816(O[2 * ntp + 1], ph, &vb4[2]);
            }
        }

        // commit prefetched tile into the other stage, one sync per iteration
        if (jt < qt) {
            const int nxt = cur ^ 1;
#pragma unroll
            for (int i = 0; i < 4; i++) {
                *(uint4*)&sK[nxt][lr][lc + i * 8] = kreg[i];
                *(uint4*)&sV[nxt][lr][lc + i * 8] = vreg[i];
            }
        }
        __syncthreads();
    }

    const float i0 = 1.0f / l0;
    const float i1 = 1.0f / l1;
    const int h = hb & (NH - 1);
    const int b = hb >> 4;
    const int s0 = q0 + w * 16 + (lane >> 2);
    const size_t r0 = (size_t)(b * SEQ + s0) * D_MODEL + h * DK + (lane & 3) * 2;
    const size_t r1 = r0 + 8ull * D_MODEL;
#pragma unroll
    for (int nt = 0; nt < 8; nt++) {
        u32 h2, l2;
        split2h(O[nt][0] * i0, O[nt][1] * i0, &h2, &l2);
        *(u32*)&ohi[r0 + nt * 8] = h2;
        *(u32*)&olo[r0 + nt * 8] = l2;
        split2h(O[nt][2] * i1, O[nt][3] * i1, &h2, &l2);
        *(u32*)&ohi[r1 + nt * 8] = h2;
        *(u32*)&olo[r1 + nt * 8] = l2;
    }
}

// ---------------------------------------------------------------------------
extern "C" void kernel_launch(void* const* d_in, const int* in_sizes, int n_in,
                              void* d_out, int out_size)
{
    const float* x  = (const float*)d_in[0];
    const float* Wq = (const float*)d_in[1];
    const float* Wk = (const float*)d_in[2];
    const float* Wv = (const float*)d_in[3];
    const float* Wo = (const float*)d_in[4];
    float* out = (float*)d_out;

    __half* xh = 0;
    __half* xl = 0;
    __half* ah = 0;
    __half* al = 0;
    __half* wh = 0;
    cudaGetSymbolAddress((void**)&xh, g_xh);
    cudaGetSymbolAddress((void**)&xl, g_xl);
    cudaGetSymbolAddress((void**)&ah, g_ah);
    cudaGetSymbolAddress((void**)&al, g_al);
    cudaGetSymbolAddress((void**)&wh, g_wh);

    __half* qh = 0;
    __half* ql = 0;
    __half* kh = 0;
    __half* vh = 0;
    cudaGetSymbolAddress((void**)&qh, g_qh);
    cudaGetSymbolAddress((void**)&ql, g_ql);
    cudaGetSymbolAddress((void**)&kh, g_kh);
    cudaGetSymbolAddress((void**)&vh, g_vh);

    const size_t WSZ = (size_t)D_MODEL * D_MODEL;
    const int wN4 = (int)(WSZ / 4);
    const int xN4 = M_ROWS * D_MODEL / 4;
    const int wBlocks = (wN4 + 255) / 256;
    const int xBlocks = (xN4 + 255) / 256;

    dim3 wgrid(wBlocks, 4);
    convert_w4<<<wgrid, 256>>>(Wq, Wk, Wv, Wo, wh, wN4);
    split_x<<<xBlocks, 256>>>(x, xh, xl, xN4);

    // fused QKV projection + RoPE + relayout (no fp32 round-trip)
    dim3 gqkv(3 * D_MODEL / BN, M_ROWS / BM);       // (24, 32)
    gemm_2p<1><<<gqkv, 256>>>(xh, xl, wh, (float*)0, qh, ql, kh, vh,
                              M_ROWS, 3 * D_MODEL, D_MODEL);

    dim3 agrid(SEQ / 64, NH * BATCH);               // (32, 32)
    attn_mma<<<agrid, 128>>>(qh, ql, kh, vh, ah, al);

    // output projection: [4096][1024] = attn @ Wo^T
    dim3 go(D_MODEL / BN, M_ROWS / BM);             // (8, 32)
    gemm_2p<0><<<go, 256>>>(ah, al, wh + 3 * WSZ, out, (__half*)0, (__half*)0,
                            (__half*)0, (__half*)0, M_ROWS, D_MODEL, D_MODEL);
}

// round 17
// speedup vs baseline: 1.0700x; 1.0700x over previous
#include <cuda_runtime.h>
#include <cuda_fp16.h>
#include <cstdint>
#include <math.h>

typedef unsigned int u32;

#define D_MODEL 1024
#define NH 16
#define DK 64
#define BATCH 2
#define SEQ 2048
#define M_ROWS (BATCH * SEQ)   // 4096

#define NEG_INF (__int_as_float(0xff800000))
#define LOG2_10000 13.287712379549449f
#define SCALE_Q 0.1803368801111244f   // 0.125 * log2(e): base-2 softmax

// ---------------------------------------------------------------------------
// Scratch
// ---------------------------------------------------------------------------
__device__ __half g_xh[(size_t)M_ROWS * D_MODEL];
__device__ __half g_xl[(size_t)M_ROWS * D_MODEL];
__device__ __half g_ah[(size_t)M_ROWS * D_MODEL];
__device__ __half g_al[(size_t)M_ROWS * D_MODEL];
__device__ __half g_wh[4ull * D_MODEL * D_MODEL];

#define HM_ELEMS ((size_t)BATCH * NH * SEQ * DK)
__device__ __half g_qh[HM_ELEMS];
__device__ __half g_ql[HM_ELEMS];
__device__ __half g_kh[HM_ELEMS];
__device__ __half g_vh[HM_ELEMS];

// ---------------------------------------------------------------------------
// helpers
// ---------------------------------------------------------------------------
__device__ __forceinline__ void split2h(float a, float b, u32* hp, u32* lp)
{
    __half2 h = __floats2half2_rn(a, b);
    float2 hf = __half22float2(h);
    __half2 l = __floats2half2_rn(a - hf.x, b - hf.y);
    *hp = *(u32*)&h;
    *lp = *(u32*)&l;
}

__device__ __forceinline__ u32 pack2h(float a, float b)
{
    __half2 h = __floats2half2_rn(a, b);
    return *(u32*)&h;
}

__device__ __forceinline__ void ldsm_x4(u32* r, const __half* p)
{
    u32 a = (u32)__cvta_generic_to_shared(p);
    asm volatile("ldmatrix.sync.aligned.m8n8.x4.shared.b16 {%0,%1,%2,%3}, [%4];"
        : "=r"(r[0]), "=r"(r[1]), "=r"(r[2]), "=r"(r[3]) : "r"(a));
}

__device__ __forceinline__ void ldsm_x4t(u32* r, const __half* p)
{
    u32 a = (u32)__cvta_generic_to_shared(p);
    asm volatile("ldmatrix.sync.aligned.m8n8.x4.trans.shared.b16 {%0,%1,%2,%3}, [%4];"
        : "=r"(r[0]), "=r"(r[1]), "=r"(r[2]), "=r"(r[3]) : "r"(a));
}

__device__ __forceinline__ void mma16816(float* d, const u32* a, const u32* b)
{
    asm volatile("mma.sync.aligned.m16n8k16.row.col.f32.f16.f16.f32 "
        "{%0,%1,%2,%3}, {%4,%5,%6,%7}, {%8,%9}, {%0,%1,%2,%3};"
        : "+f"(d[0]), "+f"(d[1]), "+f"(d[2]), "+f"(d[3])
        : "r"(a[0]), "r"(a[1]), "r"(a[2]), "r"(a[3]), "r"(b[0]), "r"(b[1]));
}

// ---------------------------------------------------------------------------
// Splits / converts
// ---------------------------------------------------------------------------
__global__ void split_x(const float* __restrict__ in,
                        __half* __restrict__ hi, __half* __restrict__ lo, int n4)
{
    int i = blockIdx.x * blockDim.x + threadIdx.x;
    if (i >= n4) return;
    float4 v = ((const float4*)in)[i];
    u32 h0, l0, h1, l1;
    split2h(v.x, v.y, &h0, &l0);
    split2h(v.z, v.w, &h1, &l1);
    u32* hp = (u32*)(hi + 4 * (size_t)i);
    u32* lp = (u32*)(lo + 4 * (size_t)i);
    hp[0] = h0;
    hp[1] = h1;
    lp[0] = l0;
    lp[1] = l1;
}

__global__ void convert_w4(const float* __restrict__ W0, const float* __restrict__ W1,
                           const float* __restrict__ W2, const float* __restrict__ W3,
                           __half* __restrict__ out, int n4)
{
    int i = blockIdx.x * blockDim.x + threadIdx.x;
    if (i >= n4) return;
    int wsel = blockIdx.y;
    const float* W = (wsel == 0) ? W0 : (wsel == 1) ? W1 : (wsel == 2) ? W2 : W3;
    size_t off = (size_t)wsel * D_MODEL * D_MODEL;
    float4 v = ((const float4*)W)[i];
    __half2 h0 = __floats2half2_rn(v.x, v.y);
    __half2 h1 = __floats2half2_rn(v.z, v.w);
    u32* hp = (u32*)(out + off + 4 * (size_t)i);
    hp[0] = *(u32*)&h0;
    hp[1] = *(u32*)&h1;
}

// ---------------------------------------------------------------------------
// 2-pass fp16 GEMM, 128x128 tile; B fragments via ldmatrix.x4 (2 nt per op).
//   MODE 0: plain fp32 C store.
//   MODE 1: fused QKV epilogue — RoPE(Q,K) + fp16 convert/split + head-major.
// ---------------------------------------------------------------------------
#define BM 128
#define BN 128
#define BKT 32
#define LDT 40

template<int MODE>
__global__ void __launch_bounds__(256) gemm_2p(
    const __half* __restrict__ Ahi, const __half* __restrict__ Alo,
    const __half* __restrict__ B,
    float* __restrict__ C,
    __half* __restrict__ qh, __half* __restrict__ ql,
    __half* __restrict__ kh, __half* __restrict__ vh,
    int M, int N, int K)
{
    __shared__ __align__(16) __half sAh[BM][LDT];
    __shared__ __align__(16) __half sAl[BM][LDT];
    __shared__ __align__(16) __half sB[BN][LDT];

    const int tid  = threadIdx.x;
    const int lane = tid & 31;
    const int warp = tid >> 5;
    const int m0 = blockIdx.y * BM;
    const int n0 = blockIdx.x * BN;
    const int wm = (warp & 1) * 64;
    const int wn = (warp >> 1) * 32;

    float acc[4][4][4];
#pragma unroll
    for (int mt = 0; mt < 4; mt++) {
#pragma unroll
        for (int nt = 0; nt < 4; nt++) {
#pragma unroll
            for (int q = 0; q < 4; q++) {
                acc[mt][nt][q] = 0.f;
            }
        }
    }

    for (int k0 = 0; k0 < K; k0 += BKT) {
#pragma unroll
        for (int p = 0; p < 2; p++) {
            int idx = tid + p * 256;
            int r = idx >> 2;
            int c = (idx & 3) * 8;
            *(uint4*)&sAh[r][c] = *(const uint4*)&Ahi[(size_t)(m0 + r) * K + k0 + c];
            *(uint4*)&sAl[r][c] = *(const uint4*)&Alo[(size_t)(m0 + r) * K + k0 + c];
            *(uint4*)&sB[r][c]  = *(const uint4*)&B[(size_t)(n0 + r) * K + k0 + c];
        }
        __syncthreads();

#pragma unroll
        for (int ks = 0; ks < 2; ks++) {
            const int kk = ks * 16;
            u32 ah[4][4];
            u32 al[4][4];
            u32 bb[2][4];
#pragma unroll
            for (int mt = 0; mt < 4; mt++) {
                const int rr = wm + mt * 16 + (lane & 15);
                const int cc = kk + (lane >> 4) * 8;
                ldsm_x4(ah[mt], &sAh[rr][cc]);
                ldsm_x4(al[mt], &sAl[rr][cc]);
            }
#pragma unroll
            for (int nt2 = 0; nt2 < 2; nt2++) {
                const int rr = wn + nt2 * 16 + ((lane >> 4) & 1) * 8 + (lane & 7);
                const int cc = kk + ((lane >> 3) & 1) * 8;
                ldsm_x4(bb[nt2], &sB[rr][cc]);
            }
#pragma unroll
            for (int mt = 0; mt < 4; mt++) {
#pragma unroll
                for (int nt2 = 0; nt2 < 2; nt2++) {
                    mma16816(acc[mt][nt2 * 2],     ah[mt], &bb[nt2][0]);
                    mma16816(acc[mt][nt2 * 2],     al[mt], &bb[nt2][0]);
                    mma16816(acc[mt][nt2 * 2 + 1], ah[mt], &bb[nt2][2]);
                    mma16816(acc[mt][nt2 * 2 + 1], al[mt], &bb[nt2][2]);
                }
            }
        }
        __syncthreads();
    }

    if (MODE == 0) {
#pragma unroll
        for (int mt = 0; mt < 4; mt++) {
#pragma unroll
            for (int nt = 0; nt < 4; nt++) {
                const int row = m0 + wm + mt * 16 + (lane >> 2);
                const int col = n0 + wn + nt * 8 + (lane & 3) * 2;
                float2 v0;
                v0.x = acc[mt][nt][0];
                v0.y = acc[mt][nt][1];
                float2 v1;
                v1.x = acc[mt][nt][2];
                v1.y = acc[mt][nt][3];
                *(float2*)&C[(size_t)row * N + col] = v0;
                *(float2*)&C[(size_t)(row + 8) * N + col] = v1;
            }
        }
    } else {
        // fused QKV epilogue: col in [0,3072): 0-1023 Q, 1024-2047 K, 2048-3071 V
#pragma unroll
        for (int nt = 0; nt < 4; nt++) {
            const int col = n0 + wn + nt * 8 + (lane & 3) * 2;
            const int wsel = col >> 10;
            const int hcol = col & 1023;
            const int hh = hcol >> 6;
            const int d = hcol & 63;     // even element of the RoPE pair
            const float freq = exp2f(-((float)d / 64.0f) * LOG2_10000);
#pragma unroll
            for (int mt = 0; mt < 4; mt++) {
#pragma unroll
                for (int half_i = 0; half_i < 2; half_i++) {
                    const int row = m0 + wm + mt * 16 + (lane >> 2) + half_i * 8;
                    const int s = row & (SEQ - 1);
                    const int b = row >> 11;
                    const float v0 = acc[mt][nt][half_i * 2];
                    const float v1 = acc[mt][nt][half_i * 2 + 1];
                    const size_t dst =
                        ((size_t)(b * NH + hh) * SEQ + s) * DK + d;
                    if (wsel == 0) {
                        float sn, cc;
                        __sincosf((float)s * freq, &sn, &cc);
                        float r1 = (v0 * cc - v1 * sn) * SCALE_Q;
                        float r2 = (v0 * sn + v1 * cc) * SCALE_Q;
                        u32 h2, l2;
                        split2h(r1, r2, &h2, &l2);
                        *(u32*)&qh[dst] = h2;
                        *(u32*)&ql[dst] = l2;
                    } else if (wsel == 1) {
                        float sn, cc;
                        __sincosf((float)s * freq, &sn, &cc);
                        float r1 = v0 * cc - v1 * sn;
                        float r2 = v0 * sn + v1 * cc;
                        *(u32*)&kh[dst] = pack2h(r1, r2);
                    } else {
                        *(u32*)&vh[dst] = pack2h(v0, v1);
                    }
                }
            }
        }
    }
}

// ---------------------------------------------------------------------------
// MMA flash attention v4 (R14 exact — best measured config):
//  - Q (hi/lo) resident in smem; fragments re-materialized per kc-pair
//    -> 96 regs -> 5 CTAs/SM via __launch_bounds__(128, 5)
//  - base-2 softmax (log2e folded into Q scale at projection)
//  - P single fp16 in PV; wide ldmatrix; longest-first scheduling
// ---------------------------------------------------------------------------
__global__ void __launch_bounds__(128, 5) attn_mma(
    const __half* __restrict__ qh_, const __half* __restrict__ ql_,
    const __half* __restrict__ kh_, const __half* __restrict__ vh_,
    __half* __restrict__ ohi, __half* __restrict__ olo)
{
    __shared__ __align__(16) __half sQh[64][72];
    __shared__ __align__(16) __half sQl[64][72];
    __shared__ __align__(16) __half sK[64][72];
    __shared__ __align__(16) __half sV[64][72];

    const int qt = gridDim.x - 1 - blockIdx.x;   // longest-first
    const int hb = blockIdx.y;
    const int t = threadIdx.x;
    const int lane = t & 31;
    const int w = t >> 5;
    const size_t base = (size_t)hb * (SEQ * DK);
    const int q0 = qt * 64;

    // Q tile resident in smem for the whole CTA lifetime
    for (int i = t; i < 512; i += 128) {
        int r = i >> 3, c = (i & 7) * 8;
        *(uint4*)&sQh[r][c] = *(const uint4*)&qh_[base + (size_t)(q0 + r) * DK + c];
        *(uint4*)&sQl[r][c] = *(const uint4*)&ql_[base + (size_t)(q0 + r) * DK + c];
    }

    float m0 = NEG_INF, m1 = NEG_INF, l0 = 0.f, l1 = 0.f;
    float O[8][4];
#pragma unroll
    for (int nt = 0; nt < 8; nt++) {
#pragma unroll
        for (int q = 0; q < 4; q++) O[nt][q] = 0.f;
    }

    for (int jt = 0; jt <= qt; jt++) {
        const int k0r = jt * 64;
        __syncthreads();
        for (int i = t; i < 512; i += 128) {
            int r = i >> 3, c = (i & 7) * 8;
            size_t g = base + (size_t)(k0r + r) * DK + c;
            *(uint4*)&sK[r][c] = *(const uint4*)&kh_[g];
            *(uint4*)&sV[r][c] = *(const uint4*)&vh_[g];
        }
        __syncthreads();

        // S = Q @ K^T; Q fragments re-materialized per kc-pair (16 live regs)
        float S[8][4];
#pragma unroll
        for (int nt = 0; nt < 8; nt++) {
#pragma unroll
            for (int q = 0; q < 4; q++) S[nt][q] = 0.f;
        }
#pragma unroll
        for (int kcp = 0; kcp < 2; kcp++) {
            u32 qfh[2][4];
            u32 qfl[2][4];
#pragma unroll
            for (int kk = 0; kk < 2; kk++) {
                const int kc = kcp * 2 + kk;
                const int rr = w * 16 + (lane & 15);
                const int cc = kc * 16 + (lane >> 4) * 8;
                ldsm_x4(qfh[kk], &sQh[rr][cc]);
                ldsm_x4(qfl[kk], &sQl[rr][cc]);
            }
#pragma unroll
            for (int nt = 0; nt < 8; nt++) {
                u32 kb[4];
                const int rr = nt * 8 + (lane & 7);
                ldsm_x4(kb, &sK[rr][kcp * 32 + (lane >> 3) * 8]);
                mma16816(S[nt], qfh[0], &kb[0]);
                mma16816(S[nt], qfl[0], &kb[0]);
                mma16816(S[nt], qfh[1], &kb[2]);
                mma16816(S[nt], qfl[1], &kb[2]);
            }
        }

        // causal mask + online softmax (base 2)
        const bool diag = (jt == qt);
        const int rowm = w * 16 + (lane >> 2);
        float tm0 = NEG_INF, tm1 = NEG_INF;
#pragma unroll
        for (int nt = 0; nt < 8; nt++) {
            const int cn = nt * 8 + (lane & 3) * 2;
            if (diag) {
                if (cn > rowm)         S[nt][0] = NEG_INF;
                if (cn + 1 > rowm)     S[nt][1] = NEG_INF;
                if (cn > rowm + 8)     S[nt][2] = NEG_INF;
                if (cn + 1 > rowm + 8) S[nt][3] = NEG_INF;
            }
            tm0 = fmaxf(tm0, fmaxf(S[nt][0], S[nt][1]));
            tm1 = fmaxf(tm1, fmaxf(S[nt][2], S[nt][3]));
        }
        tm0 = fmaxf(tm0, __shfl_xor_sync(0xffffffffu, tm0, 1));
        tm0 = fmaxf(tm0, __shfl_xor_sync(0xffffffffu, tm0, 2));
        tm1 = fmaxf(tm1, __shfl_xor_sync(0xffffffffu, tm1, 1));
        tm1 = fmaxf(tm1, __shfl_xor_sync(0xffffffffu, tm1, 2));

        const float mn0 = fmaxf(m0, tm0);
        const float mn1 = fmaxf(m1, tm1);
        const float a0 = exp2f(m0 - mn0);
        const float a1 = exp2f(m1 - mn1);

        float ps0 = 0.f, ps1 = 0.f;
#pragma unroll
        for (int nt = 0; nt < 8; nt++) {
            S[nt][0] = exp2f(S[nt][0] - mn0);
            S[nt][1] = exp2f(S[nt][1] - mn0);
            S[nt][2] = exp2f(S[nt][2] - mn1);
            S[nt][3] = exp2f(S[nt][3] - mn1);
            ps0 += S[nt][0] + S[nt][1];
            ps1 += S[nt][2] + S[nt][3];
        }
        ps0 += __shfl_xor_sync(0xffffffffu, ps0, 1);
        ps0 += __shfl_xor_sync(0xffffffffu, ps0, 2);
        ps1 += __shfl_xor_sync(0xffffffffu, ps1, 1);
        ps1 += __shfl_xor_sync(0xffffffffu, ps1, 2);
        l0 = l0 * a0 + ps0;
        l1 = l1 * a1 + ps1;
#pragma unroll
        for (int nt = 0; nt < 8; nt++) {
            O[nt][0] *= a0;
            O[nt][1] *= a0;
            O[nt][2] *= a1;
            O[nt][3] *= a1;
        }
        m0 = mn0;
        m1 = mn1;

        // O += P @ V, single-pass P fp16
#pragma unroll
        for (int kc = 0; kc < 4; kc++) {
            u32 ph[4];
            ph[0] = pack2h(S[2 * kc][0], S[2 * kc][1]);
            ph[1] = pack2h(S[2 * kc][2], S[2 * kc][3]);
            ph[2] = pack2h(S[2 * kc + 1][0], S[2 * kc + 1][1]);
            ph[3] = pack2h(S[2 * kc + 1][2], S[2 * kc + 1][3]);
            const int rr = kc * 16 + (lane & 15);
#pragma unroll
            for (int ntp = 0; ntp < 4; ntp++) {
                u32 vb4[4];
                ldsm_x4t(vb4, &sV[rr][ntp * 16 + (lane >> 4) * 8]);
                mma16816(O[2 * ntp],     ph, &vb4[0]);
                mma16816(O[2 * ntp + 1], ph, &vb4[2]);
            }
        }
    }

    const float i0 = 1.0f / l0;
    const float i1 = 1.0f / l1;
    const int h = hb & (NH - 1);
    const int b = hb >> 4;
    const int s0 = q0 + w * 16 + (lane >> 2);
    const size_t r0 = (size_t)(b * SEQ + s0) * D_MODEL + h * DK + (lane & 3) * 2;
    const size_t r1 = r0 + 8ull * D_MODEL;
#pragma unroll
    for (int nt = 0; nt < 8; nt++) {
        u32 h2, l2;
        split2h(O[nt][0] * i0, O[nt][1] * i0, &h2, &l2);
        *(u32*)&ohi[r0 + nt * 8] = h2;
        *(u32*)&olo[r0 + nt * 8] = l2;
        split2h(O[nt][2] * i1, O[nt][3] * i1, &h2, &l2);
        *(u32*)&ohi[r1 + nt * 8] = h2;
        *(u32*)&olo[r1 + nt * 8] = l2;
    }
}

// ---------------------------------------------------------------------------
extern "C" void kernel_launch(void* const* d_in, const int* in_sizes, int n_in,
                              void* d_out, int out_size)
{
    const float* x  = (const float*)d_in[0];
    const float* Wq = (const float*)d_in[1];
    const float* Wk = (const float*)d_in[2];
    const float* Wv = (const float*)d_in[3];
    const float* Wo = (const float*)d_in[4];
    float* out = (float*)d_out;

    __half* xh = 0;
    __half* xl = 0;
    __half* ah = 0;
    __half* al = 0;
    __half* wh = 0;
    cudaGetSymbolAddress((void**)&xh, g_xh);
    cudaGetSymbolAddress((void**)&xl, g_xl);
    cudaGetSymbolAddress((void**)&ah, g_ah);
    cudaGetSymbolAddress((void**)&al, g_al);
    cudaGetSymbolAddress((void**)&wh, g_wh);

    __half* qh = 0;
    __half* ql = 0;
    __half* kh = 0;
    __half* vh = 0;
    cudaGetSymbolAddress((void**)&qh, g_qh);
    cudaGetSymbolAddress((void**)&ql, g_ql);
    cudaGetSymbolAddress((void**)&kh, g_kh);
    cudaGetSymbolAddress((void**)&vh, g_vh);

    const size_t WSZ = (size_t)D_MODEL * D_MODEL;
    const int wN4 = (int)(WSZ / 4);
    const int xN4 = M_ROWS * D_MODEL / 4;
    const int wBlocks = (wN4 + 255) / 256;
    const int xBlocks = (xN4 + 255) / 256;

    dim3 wgrid(wBlocks, 4);
    convert_w4<<<wgrid, 256>>>(Wq, Wk, Wv, Wo, wh, wN4);
    split_x<<<xBlocks, 256>>>(x, xh, xl, xN4);

    // fused QKV projection + RoPE + relayout (no fp32 round-trip)
    dim3 gqkv(3 * D_MODEL / BN, M_ROWS / BM);       // (24, 32)
    gemm_2p<1><<<gqkv, 256>>>(xh, xl, wh, (float*)0, qh, ql, kh, vh,
                              M_ROWS, 3 * D_MODEL, D_MODEL);

    dim3 agrid(SEQ / 64, NH * BATCH);               // (32, 32)
    attn_mma<<<agrid, 128>>>(qh, ql, kh, vh, ah, al);

    // output projection: [4096][1024] = attn @ Wo^T
    dim3 go(D_MODEL / BN, M_ROWS / BM);             // (8, 32)
    gemm_2p<0><<<go, 256>>>(ah, al, wh + 3 * WSZ, out, (__half*)0, (__half*)0,
                            (__half*)0, (__half*)0, M_ROWS, D_MODEL, D_MODEL);
}